// round 13
// baseline (speedup 1.0000x reference)
#include <cuda_runtime.h>
#include <cuda_fp16.h>
#include <cstdint>

// ---------------------------------------------------------------------------
// Problem constants
// ---------------------------------------------------------------------------
#define B_BATCH  16
#define L_LEN    320000
#define NFFT     2048
#define HOP      512
#define KFREQ    1025                     // N_FFT/2 + 1
#define T_FRAMES 626
#define M_ROWS   (B_BATCH * T_FRAMES)     // 10016
#define M_PAD    10112                    // 79 * 128
// Cooley-Tukey: n = n1 + 64*n2 ; Y[m,n1,r] = sum_n2 xw[n1+64n2] w32^{n2 r}
//                X[m,k] = sum_n1 Y[m,n1,k&31] * w2048^{n1 k}
// Column order stage1: j = 2*r + c (c: 0=re, 1=im). kk order stage2: kk = 2*n1 + c.
#define S2_NB    72                       // padded stage-2 N (66 used)

// Scratch (__device__ globals — allocation-free rule)
__device__ __align__(16) __half g_y[(size_t)M_ROWS * 4096];      // ~82 MB [m][r][2*n1+c]
__device__ __align__(16) __half g_z[(size_t)32 * M_PAD * S2_NB]; // ~46 MB [r][m][j] fp16
__device__ __align__(16) __half g_b1[32 * 64];                   // [n2][j], j=2r+c
__device__ __align__(16) __half g_b2[32 * 128 * S2_NB];          // [r][kk][j], kk=2n1+c
__device__ float  g_win[NFFT];

// ---------------------------------------------------------------------------
// PTX helpers
// ---------------------------------------------------------------------------
__device__ __forceinline__ uint32_t swz128(uint32_t off) {
    return off ^ ((off >> 3) & 0x70);
}
__device__ __forceinline__ void cp16(uint32_t dst, const void* src) {
    asm volatile("cp.async.cg.shared.global [%0], [%1], 16;\n"
                 :: "r"(dst), "l"(src));
}
__device__ __forceinline__ void cp16_pred(uint32_t dst, const void* src, bool ok) {
    int sz = ok ? 16 : 0;
    asm volatile("cp.async.cg.shared.global [%0], [%1], 16, %2;\n"
                 :: "r"(dst), "l"(src), "r"(sz));
}
__device__ __forceinline__ void cp_wait_all() {
    asm volatile("cp.async.commit_group;\n" ::: "memory");
    asm volatile("cp.async.wait_group 0;\n" ::: "memory");
}
__device__ __forceinline__ void ldsm_x4(uint32_t* r, uint32_t addr) {
    asm volatile("ldmatrix.sync.aligned.m8n8.x4.shared.b16 {%0,%1,%2,%3}, [%4];\n"
                 : "=r"(r[0]), "=r"(r[1]), "=r"(r[2]), "=r"(r[3]) : "r"(addr));
}
__device__ __forceinline__ void ldsm_x4_t(uint32_t& r0, uint32_t& r1,
                                          uint32_t& r2, uint32_t& r3,
                                          uint32_t addr) {
    asm volatile("ldmatrix.sync.aligned.m8n8.x4.trans.shared.b16 {%0,%1,%2,%3}, [%4];\n"
                 : "=r"(r0), "=r"(r1), "=r"(r2), "=r"(r3) : "r"(addr));
}
__device__ __forceinline__ void ldsm_x2_t(uint32_t& r0, uint32_t& r1,
                                          uint32_t addr) {
    asm volatile("ldmatrix.sync.aligned.m8n8.x2.trans.shared.b16 {%0,%1}, [%2];\n"
                 : "=r"(r0), "=r"(r1) : "r"(addr));
}
__device__ __forceinline__ void mma16816(float* d, const uint32_t* a,
                                         const uint32_t* b) {
    asm volatile(
        "mma.sync.aligned.m16n8k16.row.col.f32.f16.f16.f32 "
        "{%0,%1,%2,%3}, {%4,%5,%6,%7}, {%8,%9}, {%0,%1,%2,%3};\n"
        : "+f"(d[0]), "+f"(d[1]), "+f"(d[2]), "+f"(d[3])
        : "r"(a[0]), "r"(a[1]), "r"(a[2]), "r"(a[3]), "r"(b[0]), "r"(b[1]));
}

// ---------------------------------------------------------------------------
// Merged prep: window + B1 + B2
// ---------------------------------------------------------------------------
__global__ void prep_all_kernel() {
    int i = blockIdx.x * blockDim.x + threadIdx.x;
    const int total_b2 = 32 * 128 * S2_NB;
    if (i < total_b2) {
        int r   = i / (128 * S2_NB);
        int rem = i - r * (128 * S2_NB);
        int kk  = rem / S2_NB;
        int j   = rem - kk * S2_NB;
        float v = 0.0f;
        if (j < 66) {
            int n1 = kk >> 1;              // kk = 2*n1 + c
            int k  = (j >> 1) * 32 + r;
            float s, c;
            sincospif((float)(n1 * k) / 1024.0f, &s, &c);
            bool im_in  = (kk & 1) != 0;
            bool im_out = (j & 1) != 0;
            v = im_in ? (im_out ? c : s) : (im_out ? -s : c);
        }
        g_b2[i] = __float2half(v);
    }
    if (i < NFFT)
        g_win[i] = 0.5f - 0.5f * cospif((float)i / 1024.0f);
    if (i >= NFFT && i < NFFT + 32 * 64) {
        int t = i - NFFT;
        int n2 = t >> 6, j = t & 63;
        int r = j >> 1;                    // j = 2*r + c
        float s, c;
        sincospif((float)(n2 * r) / 16.0f, &s, &c);
        g_b1[t] = __float2half((j & 1) ? -s : c);
    }
}

// ---------------------------------------------------------------------------
// Stage 1 (fused framing + DFT32 GEMM): CTA = 4 frames, 512 threads, 16 warps.
// Warp tile 32 rows x 32 cols -> acc 32 regs -> 2 CTAs/SM (50% occ).
// sY layout: [mloc][r*144 + 2*n1 + c]  (half2 stores, conflict-free)
// ---------------------------------------------------------------------------
#define SY_RSLICE 144
#define SY_MLOC   (32 * SY_RSLICE)        // 4608 halves per frame
#define S1_SMEM   (4 * SY_MLOC * 2)       // 36864 B
__global__ __launch_bounds__(512, 2)
void stage1_kernel(const float* __restrict__ x) {
    extern __shared__ char smem[];
    __half* sY = (__half*)smem;
    const uint32_t sAb = (uint32_t)__cvta_generic_to_shared(smem);
    const uint32_t sBb = sAb + 16384;

    const int tid = threadIdx.x;
    const int wid = tid >> 5, lane = tid & 31;
    const int bm = blockIdx.x;

    // B1 -> smem (SW128): 256 x 16B chunks, first 256 threads
    if (tid < 256) {
        int row = tid >> 3, c8 = tid & 7;
        uint4 v = *reinterpret_cast<const uint4*>(&g_b1[row * 64 + c8 * 8]);
        *reinterpret_cast<uint4*>(smem + 16384 +
            swz128((uint32_t)(row * 128 + c8 * 16))) = v;
    }

    // direct load + window + transpose -> sA. thread = (row, c16-half).
    {
        const int row = tid >> 1;              // 0..255
        const int hsel = tid & 1;              // c16 pair selector
        const int mloc = row >> 6, n1 = row & 63;
        const int m = bm * 4 + mloc;
        const int b = m / T_FRAMES;
        const int tf = m - b * T_FRAMES;
        const float* xb = x + (size_t)b * L_LEN;
        const int base = tf * HOP - 1024 + n1;
#pragma unroll
        for (int cc = 0; cc < 2; cc++) {
            int c16 = hsel * 2 + cc;
            __half h[8];
#pragma unroll
            for (int e = 0; e < 8; e++) {
                int n = n1 + 64 * (c16 * 8 + e);
                int jj = base + 64 * (c16 * 8 + e);
                if (jj < 0)           jj = -jj;
                else if (jj >= L_LEN) jj = 2 * (L_LEN - 1) - jj;
                h[e] = __float2half(xb[jj] * g_win[n]);
            }
            int off = row * 64 + ((c16 ^ (row & 3)) << 4);
            *reinterpret_cast<uint4*>(smem + off) =
                *reinterpret_cast<uint4*>(h);
        }
    }
    __syncthreads();

    // mma: 16 warps; rg = wid>>1 (32-row group), cg = wid&1 (32-col group)
    const int rg = wid >> 1, cg = wid & 1;
    float acc[2][4][4];
#pragma unroll
    for (int a = 0; a < 2; a++)
#pragma unroll
        for (int bb = 0; bb < 4; bb++)
#pragma unroll
            for (int q = 0; q < 4; q++) acc[a][bb][q] = 0.0f;

#pragma unroll
    for (int ks = 0; ks < 2; ks++) {
        uint32_t af[2][4];
#pragma unroll
        for (int im = 0; im < 2; im++) {
            int row = rg * 32 + im * 16 + (lane & 15);
            int c2 = (ks * 2 + (lane >> 4)) ^ (row & 3);
            ldsm_x4(af[im], sAb + row * 64 + c2 * 16);
        }
        uint32_t bf[4][2];
#pragma unroll
        for (int inp2 = 0; inp2 < 2; inp2++) {
            int krow = ks * 16 + (lane & 15);
            uint32_t addr = sBb + swz128((uint32_t)(krow * 128 + cg * 64 +
                                         inp2 * 32 + ((lane >> 4) << 4)));
            uint32_t r0, r1, r2, r3;
            ldsm_x4_t(r0, r1, r2, r3, addr);
            bf[inp2 * 2][0] = r0;     bf[inp2 * 2][1] = r1;
            bf[inp2 * 2 + 1][0] = r2; bf[inp2 * 2 + 1][1] = r3;
        }
#pragma unroll
        for (int im = 0; im < 2; im++)
#pragma unroll
            for (int in = 0; in < 4; in++)
                mma16816(acc[im][in], af[im], bf[in]);
    }
    __syncthreads();          // sA/sB dead -> sY may overwrite

    // half2 transpose epilogue: col j0 = cg*32 + in*8 + tq*2 ; r = j0>>1
    const int g = lane >> 2, tq = lane & 3;
#pragma unroll
    for (int im = 0; im < 2; im++) {
#pragma unroll
        for (int half = 0; half < 2; half++) {
            int row = rg * 32 + im * 16 + g + half * 8;
            int mloc = row >> 6, n1 = row & 63;
#pragma unroll
            for (int in = 0; in < 4; in++) {
                int r = cg * 16 + in * 4 + tq;
                __half2 hv = __floats2half2_rn(acc[im][in][half * 2],
                                               acc[im][in][half * 2 + 1]);
                *reinterpret_cast<__half2*>(
                    &sY[mloc * SY_MLOC + r * SY_RSLICE + 2 * n1]) = hv;
            }
        }
    }
    __syncthreads();

    // coalesced dump to unpadded g_y [m][r*128 + 2*n1 + c]: 2048 chunks, 4/thr
#pragma unroll
    for (int q = 0; q < 4; q++) {
        int ch = q * 512 + tid;
        int l = ch * 8;
        int mloc = l >> 12;
        int rem = l & 4095;
        int r = rem >> 7, rem2 = rem & 127;
        const uint4 v = *reinterpret_cast<const uint4*>(
            &sY[mloc * SY_MLOC + r * SY_RSLICE + rem2]);
        *reinterpret_cast<uint4*>(&g_y[(size_t)bm * 16384 + l]) = v;
    }
}

// ---------------------------------------------------------------------------
// Stage 2: per residue r: Z_r = Yr[M,128] @ B2_r[128,72] -> g_z (fp16)
// ---------------------------------------------------------------------------
#define S2_SMEM (32768 + 128 * 144)
__global__ __launch_bounds__(128)
void stage2_kernel() {
    extern __shared__ char smem[];
    const uint32_t sAb = (uint32_t)__cvta_generic_to_shared(smem);
    const uint32_t sBb = sAb + 32768;
    const int tid = threadIdx.x;
    const int wid = tid >> 5, lane = tid & 31;
    const int bm = blockIdx.x;
    const int rblk = blockIdx.y;

#pragma unroll
    for (int q = 0; q < 16; q++) {
        int i = q * 128 + tid;
        int row = i >> 4, c16 = i & 15;
        int h = c16 >> 3, c8 = c16 & 7;
        int grow = bm * 128 + row;
        int gr = grow < M_ROWS ? grow : 0;
        cp16_pred(sAb + h * 16384 + swz128((uint32_t)(row * 128 + c8 * 16)),
                  &g_y[(size_t)gr * 4096 + rblk * 128 + c16 * 8],
                  grow < M_ROWS);
    }
    {
        const __half* src = &g_b2[(size_t)rblk * 128 * S2_NB + tid * S2_NB];
#pragma unroll
        for (int cc = 0; cc < 9; cc++)
            cp16(sBb + tid * 144 + cc * 16, src + cc * 8);
    }
    cp_wait_all();
    __syncthreads();

    float acc[2][9][4];
#pragma unroll
    for (int a = 0; a < 2; a++)
#pragma unroll
        for (int bb = 0; bb < 9; bb++)
#pragma unroll
            for (int q = 0; q < 4; q++) acc[a][bb][q] = 0.0f;

#pragma unroll
    for (int ks = 0; ks < 8; ks++) {
        uint32_t af[2][4];
#pragma unroll
        for (int im = 0; im < 2; im++) {
            int row = wid * 32 + im * 16 + (lane & 15);
            int c16 = 2 * ks + (lane >> 4);
            int h = c16 >> 3, c8 = c16 & 7;
            ldsm_x4(af[im], sAb + h * 16384 +
                            swz128((uint32_t)(row * 128 + c8 * 16)));
        }
        uint32_t bf[9][2];
#pragma unroll
        for (int inp = 0; inp < 4; inp++) {
            int krow = ks * 16 + (lane & 15);
            uint32_t addr = sBb + krow * 144 + inp * 32 + ((lane >> 4) << 4);
            uint32_t r0, r1, r2, r3;
            ldsm_x4_t(r0, r1, r2, r3, addr);
            bf[inp * 2][0] = r0;     bf[inp * 2][1] = r1;
            bf[inp * 2 + 1][0] = r2; bf[inp * 2 + 1][1] = r3;
        }
        {
            int krow = ks * 16 + (lane & 15);
            ldsm_x2_t(bf[8][0], bf[8][1], sBb + krow * 144 + 128);
        }
#pragma unroll
        for (int im = 0; im < 2; im++)
#pragma unroll
            for (int in = 0; in < 9; in++)
                mma16816(acc[im][in], af[im], bf[in]);
    }

    // coalesced half2 stores to g_z[rblk][grow][j] (fp16)
    const int g = lane >> 2, tq = lane & 3;
#pragma unroll
    for (int im = 0; im < 2; im++) {
#pragma unroll
        for (int half = 0; half < 2; half++) {
            int grow = bm * 128 + wid * 32 + im * 16 + g + half * 8;
            __half* dst = &g_z[((size_t)rblk * M_PAD + grow) * S2_NB];
#pragma unroll
            for (int in = 0; in < 9; in++) {
                int j0 = in * 8 + tq * 2;
                *reinterpret_cast<__half2*>(dst + j0) =
                    __floats2half2_rn(acc[im][in][half * 2],
                                      acc[im][in][half * 2 + 1]);
            }
        }
    }
}

// ---------------------------------------------------------------------------
// Reorder: g_z[r][m][j] (fp16) -> out (fp32), div-free, 8 rows/CTA.
// smem slice 578 halves (stride 289 4B-words, odd -> conflict-free reads).
// NB: slice byte-stride 1156 is NOT 16B aligned -> smem fill uses half2 stores.
// ---------------------------------------------------------------------------
#define RB       8
#define SLICE_H  578                             // 8*72 + 2
#define RD_SMEM  (32 * SLICE_H * 2)              // 36992 B -> 6 CTAs/SM
__global__ __launch_bounds__(256)
void reorder_kernel(float* __restrict__ out) {
    extern __shared__ __half sh[];
    const int tid = threadIdx.x;
    const int m0 = blockIdx.x * RB;

#pragma unroll
    for (int q = 0; q < 9; q++) {
        int ch = q * 256 + tid;
        int r = ch / 72, w = ch - r * 72;
        uint4 v = *reinterpret_cast<const uint4*>(
            &g_z[((size_t)r * M_PAD + m0) * S2_NB + w * 8]);
        __half2* dst = reinterpret_cast<__half2*>(&sh[r * SLICE_H + w * 8]);
        dst[0] = *reinterpret_cast<const __half2*>(&v.x);
        dst[1] = *reinterpret_cast<const __half2*>(&v.y);
        dst[2] = *reinterpret_cast<const __half2*>(&v.z);
        dst[3] = *reinterpret_cast<const __half2*>(&v.w);
    }
    __syncthreads();

    const size_t imag_base = (size_t)M_ROWS * KFREQ;
#pragma unroll
    for (int mm = 0; mm < RB; mm++) {
        const int row = m0 + mm;                 // M_ROWS % RB == 0
        const __half* srow = sh + mm * S2_NB;
        float* ore = out + (size_t)row * KFREQ;
        float* oim = out + imag_base + (size_t)row * KFREQ;
#pragma unroll
        for (int q = 0; q < 5; q++) {
            int k = q * 256 + tid;
            if (k < KFREQ) {
                int r = k & 31, k2 = k >> 5;
                __half2 hv = *reinterpret_cast<const __half2*>(
                    srow + r * SLICE_H + 2 * k2);
                float2 f = __half22float2(hv);
                ore[k] = f.x;
                oim[k] = f.y;
            }
        }
    }
}

// ---------------------------------------------------------------------------
extern "C" void kernel_launch(void* const* d_in, const int* in_sizes, int n_in,
                              void* d_out, int out_size) {
    const float* x = (const float*)d_in[0];
    float* out = (float*)d_out;

    cudaFuncSetAttribute(stage1_kernel,
                         cudaFuncAttributeMaxDynamicSharedMemorySize, S1_SMEM);
    cudaFuncSetAttribute(stage2_kernel,
                         cudaFuncAttributeMaxDynamicSharedMemorySize, S2_SMEM);
    cudaFuncSetAttribute(reorder_kernel,
                         cudaFuncAttributeMaxDynamicSharedMemorySize, RD_SMEM);

    prep_all_kernel<<<(32 * 128 * S2_NB + 255) / 256, 256>>>();

    stage1_kernel<<<M_ROWS / 4, 512, S1_SMEM>>>(x);

    dim3 g2((M_ROWS + 127) / 128, 32);           // 79 x 32
    stage2_kernel<<<g2, 128, S2_SMEM>>>();

    reorder_kernel<<<M_ROWS / RB, 256, RD_SMEM>>>(out);
}

// round 14
// speedup vs baseline: 1.0696x; 1.0696x over previous
#include <cuda_runtime.h>
#include <cuda_fp16.h>
#include <cstdint>

// ---------------------------------------------------------------------------
// Problem constants
// ---------------------------------------------------------------------------
#define B_BATCH  16
#define L_LEN    320000
#define NFFT     2048
#define HOP      512
#define KFREQ    1025                     // N_FFT/2 + 1
#define T_FRAMES 626
#define M_ROWS   (B_BATCH * T_FRAMES)     // 10016
#define M_PAD    10112                    // 79 * 128
// Cooley-Tukey: n = n1 + 64*n2 ; Y[m,n1,r] = sum_n2 xw[n1+64n2] w32^{n2 r}
//                X[m,k] = sum_n1 Y[m,n1,k&31] * w2048^{n1 k}
// Column order stage1: j = 2*r + c (c: 0=re, 1=im). kk order stage2: kk = 2*n1 + c.
#define S2_NB    72                       // padded stage-2 N (66 used)

// Scratch (__device__ globals — allocation-free rule)
__device__ __align__(16) __half g_y[(size_t)M_ROWS * 4096];      // ~82 MB [m][r][2*n1+c]
__device__ __align__(16) __half g_z[(size_t)32 * M_PAD * S2_NB]; // ~46 MB [r][m][j] fp16
__device__ __align__(16) __half g_b1[32 * 64];                   // [n2][j], j=2r+c
__device__ __align__(16) __half g_b2[32 * 128 * S2_NB];          // [r][kk][j], kk=2n1+c
__device__ float  g_win[NFFT];

// ---------------------------------------------------------------------------
// PTX helpers
// ---------------------------------------------------------------------------
__device__ __forceinline__ uint32_t swz128(uint32_t off) {
    return off ^ ((off >> 3) & 0x70);
}
__device__ __forceinline__ void cp16(uint32_t dst, const void* src) {
    asm volatile("cp.async.cg.shared.global [%0], [%1], 16;\n"
                 :: "r"(dst), "l"(src));
}
__device__ __forceinline__ void cp16_pred(uint32_t dst, const void* src, bool ok) {
    int sz = ok ? 16 : 0;
    asm volatile("cp.async.cg.shared.global [%0], [%1], 16, %2;\n"
                 :: "r"(dst), "l"(src), "r"(sz));
}
__device__ __forceinline__ void cp_wait_all() {
    asm volatile("cp.async.commit_group;\n" ::: "memory");
    asm volatile("cp.async.wait_group 0;\n" ::: "memory");
}
__device__ __forceinline__ void ldsm_x4(uint32_t* r, uint32_t addr) {
    asm volatile("ldmatrix.sync.aligned.m8n8.x4.shared.b16 {%0,%1,%2,%3}, [%4];\n"
                 : "=r"(r[0]), "=r"(r[1]), "=r"(r[2]), "=r"(r[3]) : "r"(addr));
}
__device__ __forceinline__ void ldsm_x4_t(uint32_t& r0, uint32_t& r1,
                                          uint32_t& r2, uint32_t& r3,
                                          uint32_t addr) {
    asm volatile("ldmatrix.sync.aligned.m8n8.x4.trans.shared.b16 {%0,%1,%2,%3}, [%4];\n"
                 : "=r"(r0), "=r"(r1), "=r"(r2), "=r"(r3) : "r"(addr));
}
__device__ __forceinline__ void ldsm_x2_t(uint32_t& r0, uint32_t& r1,
                                          uint32_t addr) {
    asm volatile("ldmatrix.sync.aligned.m8n8.x2.trans.shared.b16 {%0,%1}, [%2];\n"
                 : "=r"(r0), "=r"(r1) : "r"(addr));
}
__device__ __forceinline__ void mma16816(float* d, const uint32_t* a,
                                         const uint32_t* b) {
    asm volatile(
        "mma.sync.aligned.m16n8k16.row.col.f32.f16.f16.f32 "
        "{%0,%1,%2,%3}, {%4,%5,%6,%7}, {%8,%9}, {%0,%1,%2,%3};\n"
        : "+f"(d[0]), "+f"(d[1]), "+f"(d[2]), "+f"(d[3])
        : "r"(a[0]), "r"(a[1]), "r"(a[2]), "r"(a[3]), "r"(b[0]), "r"(b[1]));
}

// ---------------------------------------------------------------------------
// Merged prep: window + B1 + B2
// ---------------------------------------------------------------------------
__global__ void prep_all_kernel() {
    int i = blockIdx.x * blockDim.x + threadIdx.x;
    const int total_b2 = 32 * 128 * S2_NB;
    if (i < total_b2) {
        int r   = i / (128 * S2_NB);
        int rem = i - r * (128 * S2_NB);
        int kk  = rem / S2_NB;
        int j   = rem - kk * S2_NB;
        float v = 0.0f;
        if (j < 66) {
            int n1 = kk >> 1;              // kk = 2*n1 + c
            int k  = (j >> 1) * 32 + r;
            float s, c;
            sincospif((float)(n1 * k) / 1024.0f, &s, &c);
            bool im_in  = (kk & 1) != 0;
            bool im_out = (j & 1) != 0;
            v = im_in ? (im_out ? c : s) : (im_out ? -s : c);
        }
        g_b2[i] = __float2half(v);
    }
    if (i < NFFT)
        g_win[i] = 0.5f - 0.5f * cospif((float)i / 1024.0f);
    if (i >= NFFT && i < NFFT + 32 * 64) {
        int t = i - NFFT;
        int n2 = t >> 6, j = t & 63;
        int r = j >> 1;                    // j = 2*r + c
        float s, c;
        sincospif((float)(n2 * r) / 16.0f, &s, &c);
        g_b1[t] = __float2half((j & 1) ? -s : c);
    }
}

// ---------------------------------------------------------------------------
// Stage 1 (fused framing + DFT32 GEMM): CTA = 4 frames (256 A-rows), 256 thr.
// Epilogue stores DIRECTLY to g_y as half2: lanes give 8 consecutive n1 per
// (warp,im,half,in) -> 4 fully-used 32B sectors per store op. No sY smem.
// ---------------------------------------------------------------------------
#define S1_SMEM (16384 + 4096)            // sA 16K | sB 4K
__global__ __launch_bounds__(256)
void stage1_kernel(const float* __restrict__ x) {
    extern __shared__ char smem[];
    const uint32_t sAb = (uint32_t)__cvta_generic_to_shared(smem);
    const uint32_t sBb = sAb + 16384;

    const int tid = threadIdx.x;
    const int wid = tid >> 5, lane = tid & 31;
    const int bm = blockIdx.x;

    // B1 -> smem (SW128)
    {
        int row = tid >> 3, c8 = tid & 7;
        uint4 v = *reinterpret_cast<const uint4*>(&g_b1[row * 64 + c8 * 8]);
        *reinterpret_cast<uint4*>(smem + 16384 +
            swz128((uint32_t)(row * 128 + c8 * 16))) = v;
    }

    // direct load + window + transpose -> sA. thread = (frame, n1).
    {
        const int mloc = tid >> 6, n1 = tid & 63;
        const int m = bm * 4 + mloc;
        const int b = m / T_FRAMES;
        const int tf = m - b * T_FRAMES;
        const float* xb = x + (size_t)b * L_LEN;
        const int base = tf * HOP - 1024 + n1;
#pragma unroll
        for (int c16 = 0; c16 < 4; c16++) {
            __half h[8];
#pragma unroll
            for (int e = 0; e < 8; e++) {
                int n = n1 + 64 * (c16 * 8 + e);
                int jj = base + 64 * (c16 * 8 + e);
                if (jj < 0)           jj = -jj;
                else if (jj >= L_LEN) jj = 2 * (L_LEN - 1) - jj;
                h[e] = __float2half(xb[jj] * g_win[n]);
            }
            int off = tid * 64 + ((c16 ^ (tid & 3)) << 4);
            *reinterpret_cast<uint4*>(smem + off) =
                *reinterpret_cast<uint4*>(h);
        }
    }
    __syncthreads();

    float acc[2][8][4];
#pragma unroll
    for (int a = 0; a < 2; a++)
#pragma unroll
        for (int bb = 0; bb < 8; bb++)
#pragma unroll
            for (int q = 0; q < 4; q++) acc[a][bb][q] = 0.0f;

#pragma unroll
    for (int ks = 0; ks < 2; ks++) {
        uint32_t af[2][4];
#pragma unroll
        for (int im = 0; im < 2; im++) {
            int row = wid * 32 + im * 16 + (lane & 15);
            int c2 = (ks * 2 + (lane >> 4)) ^ (row & 3);
            ldsm_x4(af[im], sAb + row * 64 + c2 * 16);
        }
        uint32_t bf[8][2];
#pragma unroll
        for (int inp = 0; inp < 4; inp++) {
            int krow = ks * 16 + (lane & 15);
            uint32_t addr = sBb +
                swz128((uint32_t)(krow * 128 + inp * 32 + ((lane >> 4) << 4)));
            uint32_t r0, r1, r2, r3;
            ldsm_x4_t(r0, r1, r2, r3, addr);
            bf[inp * 2][0] = r0;     bf[inp * 2][1] = r1;
            bf[inp * 2 + 1][0] = r2; bf[inp * 2 + 1][1] = r3;
        }
#pragma unroll
        for (int im = 0; im < 2; im++)
#pragma unroll
            for (int in = 0; in < 8; in++)
                mma16816(acc[im][in], af[im], bf[in]);
    }

    // direct half2 epilogue to g_y[m][r*128 + 2*n1 + c]
    // lanes: g -> 8 consecutive n1 (32B contiguous), tq -> 4 r-slices
    const int g = lane >> 2, tq = lane & 3;
#pragma unroll
    for (int im = 0; im < 2; im++) {
#pragma unroll
        for (int half = 0; half < 2; half++) {
            int row = wid * 32 + im * 16 + g + half * 8;
            int mloc = row >> 6, n1 = row & 63;
            __half* dst = &g_y[(size_t)(bm * 4 + mloc) * 4096 + 2 * n1];
#pragma unroll
            for (int in = 0; in < 8; in++) {
                int r = in * 4 + tq;
                *reinterpret_cast<__half2*>(dst + r * 128) =
                    __floats2half2_rn(acc[im][in][half * 2],
                                      acc[im][in][half * 2 + 1]);
            }
        }
    }
}

// ---------------------------------------------------------------------------
// Stage 2: per residue r: Z_r = Yr[M,128] @ B2_r[128,72] -> g_z (fp16)
// ---------------------------------------------------------------------------
#define S2_SMEM (32768 + 128 * 144)
__global__ __launch_bounds__(128)
void stage2_kernel() {
    extern __shared__ char smem[];
    const uint32_t sAb = (uint32_t)__cvta_generic_to_shared(smem);
    const uint32_t sBb = sAb + 32768;
    const int tid = threadIdx.x;
    const int wid = tid >> 5, lane = tid & 31;
    const int bm = blockIdx.x;
    const int rblk = blockIdx.y;

#pragma unroll
    for (int q = 0; q < 16; q++) {
        int i = q * 128 + tid;
        int row = i >> 4, c16 = i & 15;
        int h = c16 >> 3, c8 = c16 & 7;
        int grow = bm * 128 + row;
        int gr = grow < M_ROWS ? grow : 0;
        cp16_pred(sAb + h * 16384 + swz128((uint32_t)(row * 128 + c8 * 16)),
                  &g_y[(size_t)gr * 4096 + rblk * 128 + c16 * 8],
                  grow < M_ROWS);
    }
    {
        const __half* src = &g_b2[(size_t)rblk * 128 * S2_NB + tid * S2_NB];
#pragma unroll
        for (int cc = 0; cc < 9; cc++)
            cp16(sBb + tid * 144 + cc * 16, src + cc * 8);
    }
    cp_wait_all();
    __syncthreads();

    float acc[2][9][4];
#pragma unroll
    for (int a = 0; a < 2; a++)
#pragma unroll
        for (int bb = 0; bb < 9; bb++)
#pragma unroll
            for (int q = 0; q < 4; q++) acc[a][bb][q] = 0.0f;

#pragma unroll
    for (int ks = 0; ks < 8; ks++) {
        uint32_t af[2][4];
#pragma unroll
        for (int im = 0; im < 2; im++) {
            int row = wid * 32 + im * 16 + (lane & 15);
            int c16 = 2 * ks + (lane >> 4);
            int h = c16 >> 3, c8 = c16 & 7;
            ldsm_x4(af[im], sAb + h * 16384 +
                            swz128((uint32_t)(row * 128 + c8 * 16)));
        }
        uint32_t bf[9][2];
#pragma unroll
        for (int inp = 0; inp < 4; inp++) {
            int krow = ks * 16 + (lane & 15);
            uint32_t addr = sBb + krow * 144 + inp * 32 + ((lane >> 4) << 4);
            uint32_t r0, r1, r2, r3;
            ldsm_x4_t(r0, r1, r2, r3, addr);
            bf[inp * 2][0] = r0;     bf[inp * 2][1] = r1;
            bf[inp * 2 + 1][0] = r2; bf[inp * 2 + 1][1] = r3;
        }
        {
            int krow = ks * 16 + (lane & 15);
            ldsm_x2_t(bf[8][0], bf[8][1], sBb + krow * 144 + 128);
        }
#pragma unroll
        for (int im = 0; im < 2; im++)
#pragma unroll
            for (int in = 0; in < 9; in++)
                mma16816(acc[im][in], af[im], bf[in]);
    }

    // coalesced half2 stores to g_z[rblk][grow][j] (fp16)
    const int g = lane >> 2, tq = lane & 3;
#pragma unroll
    for (int im = 0; im < 2; im++) {
#pragma unroll
        for (int half = 0; half < 2; half++) {
            int grow = bm * 128 + wid * 32 + im * 16 + g + half * 8;
            __half* dst = &g_z[((size_t)rblk * M_PAD + grow) * S2_NB];
#pragma unroll
            for (int in = 0; in < 9; in++) {
                int j0 = in * 8 + tq * 2;
                *reinterpret_cast<__half2*>(dst + j0) =
                    __floats2half2_rn(acc[im][in][half * 2],
                                      acc[im][in][half * 2 + 1]);
            }
        }
    }
}

// ---------------------------------------------------------------------------
// Reorder: g_z[r][m][j] (fp16) -> out (fp32), div-free, 8 rows/CTA.
// smem slice 578 halves (stride 289 4B-words, odd -> conflict-free reads).
// NB: slice byte-stride 1156 is NOT 16B aligned -> smem fill uses half2 stores.
// ---------------------------------------------------------------------------
#define RB       8
#define SLICE_H  578                             // 8*72 + 2
#define RD_SMEM  (32 * SLICE_H * 2)              // 36992 B -> 6 CTAs/SM
__global__ __launch_bounds__(256)
void reorder_kernel(float* __restrict__ out) {
    extern __shared__ __half sh[];
    const int tid = threadIdx.x;
    const int m0 = blockIdx.x * RB;

#pragma unroll
    for (int q = 0; q < 9; q++) {
        int ch = q * 256 + tid;
        int r = ch / 72, w = ch - r * 72;
        uint4 v = *reinterpret_cast<const uint4*>(
            &g_z[((size_t)r * M_PAD + m0) * S2_NB + w * 8]);
        __half2* dst = reinterpret_cast<__half2*>(&sh[r * SLICE_H + w * 8]);
        dst[0] = *reinterpret_cast<const __half2*>(&v.x);
        dst[1] = *reinterpret_cast<const __half2*>(&v.y);
        dst[2] = *reinterpret_cast<const __half2*>(&v.z);
        dst[3] = *reinterpret_cast<const __half2*>(&v.w);
    }
    __syncthreads();

    const size_t imag_base = (size_t)M_ROWS * KFREQ;
#pragma unroll
    for (int mm = 0; mm < RB; mm++) {
        const int row = m0 + mm;                 // M_ROWS % RB == 0
        const __half* srow = sh + mm * S2_NB;
        float* ore = out + (size_t)row * KFREQ;
        float* oim = out + imag_base + (size_t)row * KFREQ;
#pragma unroll
        for (int q = 0; q < 5; q++) {
            int k = q * 256 + tid;
            if (k < KFREQ) {
                int r = k & 31, k2 = k >> 5;
                __half2 hv = *reinterpret_cast<const __half2*>(
                    srow + r * SLICE_H + 2 * k2);
                float2 f = __half22float2(hv);
                ore[k] = f.x;
                oim[k] = f.y;
            }
        }
    }
}

// ---------------------------------------------------------------------------
extern "C" void kernel_launch(void* const* d_in, const int* in_sizes, int n_in,
                              void* d_out, int out_size) {
    const float* x = (const float*)d_in[0];
    float* out = (float*)d_out;

    cudaFuncSetAttribute(stage1_kernel,
                         cudaFuncAttributeMaxDynamicSharedMemorySize, S1_SMEM);
    cudaFuncSetAttribute(stage2_kernel,
                         cudaFuncAttributeMaxDynamicSharedMemorySize, S2_SMEM);
    cudaFuncSetAttribute(reorder_kernel,
                         cudaFuncAttributeMaxDynamicSharedMemorySize, RD_SMEM);

    prep_all_kernel<<<(32 * 128 * S2_NB + 255) / 256, 256>>>();

    stage1_kernel<<<M_ROWS / 4, 256, S1_SMEM>>>(x);

    dim3 g2((M_ROWS + 127) / 128, 32);           // 79 x 32
    stage2_kernel<<<g2, 128, S2_SMEM>>>();

    reorder_kernel<<<M_ROWS / RB, 256, RD_SMEM>>>(out);
}

// round 15
// speedup vs baseline: 1.1984x; 1.1203x over previous
#include <cuda_runtime.h>
#include <cuda_fp16.h>
#include <cstdint>

// ---------------------------------------------------------------------------
// Problem constants
// ---------------------------------------------------------------------------
#define B_BATCH  16
#define L_LEN    320000
#define NFFT     2048
#define HOP      512
#define KFREQ    1025                     // N_FFT/2 + 1
#define T_FRAMES 626
#define M_ROWS   (B_BATCH * T_FRAMES)     // 10016
#define M_PAD    10112                    // 79 * 128
// Cooley-Tukey: n = n1 + 64*n2 ; Y[m,n1,r] = sum_n2 xw[n1+64n2] w32^{n2 r}
//                X[m,k] = sum_n1 Y[m,n1,k&31] * w2048^{n1 k}
// Real input => Y[r] = conj(Y[32-r]): store only r=0..16 (compact g_y),
// stage2 r>16 reads slice 32-r with conjugated B2 (sign folded into prep).
// Column order stage1: j = 2*r + c. kk order stage2: kk = 2*n1 + c.
#define S2_NB    72                       // padded stage-2 N (66 used)
#define YR       17                       // stored residues 0..16
#define YROW     (YR * 128)               // 2176 halves per m-row

// Scratch (__device__ globals — allocation-free rule)
__device__ __align__(16) __half g_y[(size_t)M_ROWS * YROW];      // ~43.5 MB
__device__ __align__(16) __half g_z[(size_t)32 * M_PAD * S2_NB]; // ~46 MB [r][m][j]
__device__ __align__(16) __half g_b1[32 * 64];                   // [n2][j], j=2r+c
__device__ __align__(16) __half g_b2[32 * 128 * S2_NB];          // [r_out][kk][j]
__device__ float  g_win[NFFT];

// ---------------------------------------------------------------------------
// PTX helpers
// ---------------------------------------------------------------------------
__device__ __forceinline__ uint32_t swz128(uint32_t off) {
    return off ^ ((off >> 3) & 0x70);
}
__device__ __forceinline__ void cp16(uint32_t dst, const void* src) {
    asm volatile("cp.async.cg.shared.global [%0], [%1], 16;\n"
                 :: "r"(dst), "l"(src));
}
__device__ __forceinline__ void cp16_pred(uint32_t dst, const void* src, bool ok) {
    int sz = ok ? 16 : 0;
    asm volatile("cp.async.cg.shared.global [%0], [%1], 16, %2;\n"
                 :: "r"(dst), "l"(src), "r"(sz));
}
__device__ __forceinline__ void cp_wait_all() {
    asm volatile("cp.async.commit_group;\n" ::: "memory");
    asm volatile("cp.async.wait_group 0;\n" ::: "memory");
}
__device__ __forceinline__ void ldsm_x4(uint32_t* r, uint32_t addr) {
    asm volatile("ldmatrix.sync.aligned.m8n8.x4.shared.b16 {%0,%1,%2,%3}, [%4];\n"
                 : "=r"(r[0]), "=r"(r[1]), "=r"(r[2]), "=r"(r[3]) : "r"(addr));
}
__device__ __forceinline__ void ldsm_x4_t(uint32_t& r0, uint32_t& r1,
                                          uint32_t& r2, uint32_t& r3,
                                          uint32_t addr) {
    asm volatile("ldmatrix.sync.aligned.m8n8.x4.trans.shared.b16 {%0,%1,%2,%3}, [%4];\n"
                 : "=r"(r0), "=r"(r1), "=r"(r2), "=r"(r3) : "r"(addr));
}
__device__ __forceinline__ void ldsm_x2_t(uint32_t& r0, uint32_t& r1,
                                          uint32_t addr) {
    asm volatile("ldmatrix.sync.aligned.m8n8.x2.trans.shared.b16 {%0,%1}, [%2];\n"
                 : "=r"(r0), "=r"(r1) : "r"(addr));
}
__device__ __forceinline__ void mma16816(float* d, const uint32_t* a,
                                         const uint32_t* b) {
    asm volatile(
        "mma.sync.aligned.m16n8k16.row.col.f32.f16.f16.f32 "
        "{%0,%1,%2,%3}, {%4,%5,%6,%7}, {%8,%9}, {%0,%1,%2,%3};\n"
        : "+f"(d[0]), "+f"(d[1]), "+f"(d[2]), "+f"(d[3])
        : "r"(a[0]), "r"(a[1]), "r"(a[2]), "r"(a[3]), "r"(b[0]), "r"(b[1]));
}

// ---------------------------------------------------------------------------
// Merged prep: window + B1 + B2 (B2 conjugated for r_out > 16)
// ---------------------------------------------------------------------------
__global__ void prep_all_kernel() {
    int i = blockIdx.x * blockDim.x + threadIdx.x;
    const int total_b2 = 32 * 128 * S2_NB;
    if (i < total_b2) {
        int r   = i / (128 * S2_NB);       // OUTPUT residue
        int rem = i - r * (128 * S2_NB);
        int kk  = rem / S2_NB;
        int j   = rem - kk * S2_NB;
        float v = 0.0f;
        if (j < 66) {
            int n1 = kk >> 1;              // kk = 2*n1 + c (c over SOURCE slice)
            int k  = (j >> 1) * 32 + r;
            float s, c;
            sincospif((float)(n1 * k) / 1024.0f, &s, &c);
            bool im_in  = (kk & 1) != 0;
            bool im_out = (j & 1) != 0;
            v = im_in ? (im_out ? c : s) : (im_out ? -s : c);
            if (r > 16 && im_in) v = -v;   // source slice is conj(Y[r])
        }
        g_b2[i] = __float2half(v);
    }
    if (i < NFFT)
        g_win[i] = 0.5f - 0.5f * cospif((float)i / 1024.0f);
    if (i >= NFFT && i < NFFT + 32 * 64) {
        int t = i - NFFT;
        int n2 = t >> 6, j = t & 63;
        int r = j >> 1;                    // j = 2*r + c
        float s, c;
        sincospif((float)(n2 * r) / 16.0f, &s, &c);
        g_b1[t] = __float2half((j & 1) ? -s : c);
    }
}

// ---------------------------------------------------------------------------
// Stage 1 (fused framing + DFT32 GEMM): CTA = 4 frames (256 A-rows), 256 thr.
// GEMM N = 40 cols (r<=16 + slack); sA stride 80B (conflict-free, no XOR).
// Epilogue: direct half2 stores to compact g_y (r <= 16 only).
// ---------------------------------------------------------------------------
#define SA_STRIDE 80
#define S1_SMEM   (256 * SA_STRIDE + 8192)   // sA 20480 | sB 8192
__global__ __launch_bounds__(256)
void stage1_kernel(const float* __restrict__ x) {
    extern __shared__ char smem[];
    const uint32_t sAb = (uint32_t)__cvta_generic_to_shared(smem);
    const uint32_t sBb = sAb + 256 * SA_STRIDE;

    const int tid = threadIdx.x;
    const int wid = tid >> 5, lane = tid & 31;
    const int bm = blockIdx.x;

    // B1 -> smem (SW128, 64-col layout; cols >=40 unused)
    {
        int row = tid >> 3, c8 = tid & 7;
        uint4 v = *reinterpret_cast<const uint4*>(&g_b1[row * 64 + c8 * 8]);
        *reinterpret_cast<uint4*>(smem + 256 * SA_STRIDE +
            swz128((uint32_t)(row * 128 + c8 * 16))) = v;
    }

    // direct load + window + transpose -> sA (stride 80B, no swizzle)
    {
        const int mloc = tid >> 6, n1 = tid & 63;
        const int m = bm * 4 + mloc;
        const int b = m / T_FRAMES;
        const int tf = m - b * T_FRAMES;
        const float* xb = x + (size_t)b * L_LEN;
        const int base = tf * HOP - 1024 + n1;
#pragma unroll
        for (int c16 = 0; c16 < 4; c16++) {
            __half h[8];
#pragma unroll
            for (int e = 0; e < 8; e++) {
                int n = n1 + 64 * (c16 * 8 + e);
                int jj = base + 64 * (c16 * 8 + e);
                if (jj < 0)           jj = -jj;
                else if (jj >= L_LEN) jj = 2 * (L_LEN - 1) - jj;
                h[e] = __float2half(xb[jj] * g_win[n]);
            }
            *reinterpret_cast<uint4*>(smem + tid * SA_STRIDE + c16 * 16) =
                *reinterpret_cast<uint4*>(h);
        }
    }
    __syncthreads();

    float acc[2][5][4];
#pragma unroll
    for (int a = 0; a < 2; a++)
#pragma unroll
        for (int bb = 0; bb < 5; bb++)
#pragma unroll
            for (int q = 0; q < 4; q++) acc[a][bb][q] = 0.0f;

#pragma unroll
    for (int ks = 0; ks < 2; ks++) {
        uint32_t af[2][4];
#pragma unroll
        for (int im = 0; im < 2; im++) {
            int row = wid * 32 + im * 16 + (lane & 15);
            int c2 = ks * 2 + (lane >> 4);
            ldsm_x4(af[im], sAb + row * SA_STRIDE + c2 * 16);
        }
        uint32_t bf[5][2];
#pragma unroll
        for (int inp = 0; inp < 2; inp++) {
            int krow = ks * 16 + (lane & 15);
            uint32_t addr = sBb +
                swz128((uint32_t)(krow * 128 + inp * 32 + ((lane >> 4) << 4)));
            uint32_t r0, r1, r2, r3;
            ldsm_x4_t(r0, r1, r2, r3, addr);
            bf[inp * 2][0] = r0;     bf[inp * 2][1] = r1;
            bf[inp * 2 + 1][0] = r2; bf[inp * 2 + 1][1] = r3;
        }
        {   // cols 32..39 (j 32,33 = r16 used; 34..39 discarded)
            int krow = ks * 16 + (lane & 15);
            ldsm_x2_t(bf[4][0], bf[4][1],
                      sBb + swz128((uint32_t)(krow * 128 + 64)));
        }
#pragma unroll
        for (int im = 0; im < 2; im++)
#pragma unroll
            for (int in = 0; in < 5; in++)
                mma16816(acc[im][in], af[im], bf[in]);
    }

    // direct half2 epilogue to compact g_y[m][r*128 + 2*n1 + c], r<=16
    const int g = lane >> 2, tq = lane & 3;
#pragma unroll
    for (int im = 0; im < 2; im++) {
#pragma unroll
        for (int half = 0; half < 2; half++) {
            int row = wid * 32 + im * 16 + g + half * 8;
            int mloc = row >> 6, n1 = row & 63;
            __half* dst = &g_y[(size_t)(bm * 4 + mloc) * YROW + 2 * n1];
#pragma unroll
            for (int in = 0; in < 4; in++) {
                int r = in * 4 + tq;
                *reinterpret_cast<__half2*>(dst + r * 128) =
                    __floats2half2_rn(acc[im][in][half * 2],
                                      acc[im][in][half * 2 + 1]);
            }
            if (tq == 0) {                 // in=4, r=16
                *reinterpret_cast<__half2*>(dst + 16 * 128) =
                    __floats2half2_rn(acc[im][4][half * 2],
                                      acc[im][4][half * 2 + 1]);
            }
        }
    }
}

// ---------------------------------------------------------------------------
// Stage 2: r_out = blockIdx.y; reads slice src_r = min(r,32-r) of compact g_y
// (conjugation folded into B2). Z_r -> g_z (fp16), coalesced.
// ---------------------------------------------------------------------------
#define S2_SMEM (32768 + 128 * 144)
__global__ __launch_bounds__(128)
void stage2_kernel() {
    extern __shared__ char smem[];
    const uint32_t sAb = (uint32_t)__cvta_generic_to_shared(smem);
    const uint32_t sBb = sAb + 32768;
    const int tid = threadIdx.x;
    const int wid = tid >> 5, lane = tid & 31;
    const int bm = blockIdx.x;
    const int rblk = blockIdx.y;
    const int src_r = rblk <= 16 ? rblk : 32 - rblk;

#pragma unroll
    for (int q = 0; q < 16; q++) {
        int i = q * 128 + tid;
        int row = i >> 4, c16 = i & 15;
        int h = c16 >> 3, c8 = c16 & 7;
        int grow = bm * 128 + row;
        int gr = grow < M_ROWS ? grow : 0;
        cp16_pred(sAb + h * 16384 + swz128((uint32_t)(row * 128 + c8 * 16)),
                  &g_y[(size_t)gr * YROW + src_r * 128 + c16 * 8],
                  grow < M_ROWS);
    }
    {
        const __half* src = &g_b2[(size_t)rblk * 128 * S2_NB + tid * S2_NB];
#pragma unroll
        for (int cc = 0; cc < 9; cc++)
            cp16(sBb + tid * 144 + cc * 16, src + cc * 8);
    }
    cp_wait_all();
    __syncthreads();

    float acc[2][9][4];
#pragma unroll
    for (int a = 0; a < 2; a++)
#pragma unroll
        for (int bb = 0; bb < 9; bb++)
#pragma unroll
            for (int q = 0; q < 4; q++) acc[a][bb][q] = 0.0f;

#pragma unroll
    for (int ks = 0; ks < 8; ks++) {
        uint32_t af[2][4];
#pragma unroll
        for (int im = 0; im < 2; im++) {
            int row = wid * 32 + im * 16 + (lane & 15);
            int c16 = 2 * ks + (lane >> 4);
            int h = c16 >> 3, c8 = c16 & 7;
            ldsm_x4(af[im], sAb + h * 16384 +
                            swz128((uint32_t)(row * 128 + c8 * 16)));
        }
        uint32_t bf[9][2];
#pragma unroll
        for (int inp = 0; inp < 4; inp++) {
            int krow = ks * 16 + (lane & 15);
            uint32_t addr = sBb + krow * 144 + inp * 32 + ((lane >> 4) << 4);
            uint32_t r0, r1, r2, r3;
            ldsm_x4_t(r0, r1, r2, r3, addr);
            bf[inp * 2][0] = r0;     bf[inp * 2][1] = r1;
            bf[inp * 2 + 1][0] = r2; bf[inp * 2 + 1][1] = r3;
        }
        {
            int krow = ks * 16 + (lane & 15);
            ldsm_x2_t(bf[8][0], bf[8][1], sBb + krow * 144 + 128);
        }
#pragma unroll
        for (int im = 0; im < 2; im++)
#pragma unroll
            for (int in = 0; in < 9; in++)
                mma16816(acc[im][in], af[im], bf[in]);
    }

    // coalesced half2 stores to g_z[rblk][grow][j] (fp16)
    const int g = lane >> 2, tq = lane & 3;
#pragma unroll
    for (int im = 0; im < 2; im++) {
#pragma unroll
        for (int half = 0; half < 2; half++) {
            int grow = bm * 128 + wid * 32 + im * 16 + g + half * 8;
            __half* dst = &g_z[((size_t)rblk * M_PAD + grow) * S2_NB];
#pragma unroll
            for (int in = 0; in < 9; in++) {
                int j0 = in * 8 + tq * 2;
                *reinterpret_cast<__half2*>(dst + j0) =
                    __floats2half2_rn(acc[im][in][half * 2],
                                      acc[im][in][half * 2 + 1]);
            }
        }
    }
}

// ---------------------------------------------------------------------------
// Reorder: g_z[r][m][j] (fp16) -> out (fp32), div-free, 8 rows/CTA.
// ---------------------------------------------------------------------------
#define RB       8
#define SLICE_H  578                             // 8*72 + 2
#define RD_SMEM  (32 * SLICE_H * 2)              // 36992 B
__global__ __launch_bounds__(256)
void reorder_kernel(float* __restrict__ out) {
    extern __shared__ __half sh[];
    const int tid = threadIdx.x;
    const int m0 = blockIdx.x * RB;

#pragma unroll
    for (int q = 0; q < 9; q++) {
        int ch = q * 256 + tid;
        int r = ch / 72, w = ch - r * 72;
        uint4 v = *reinterpret_cast<const uint4*>(
            &g_z[((size_t)r * M_PAD + m0) * S2_NB + w * 8]);
        __half2* dst = reinterpret_cast<__half2*>(&sh[r * SLICE_H + w * 8]);
        dst[0] = *reinterpret_cast<const __half2*>(&v.x);
        dst[1] = *reinterpret_cast<const __half2*>(&v.y);
        dst[2] = *reinterpret_cast<const __half2*>(&v.z);
        dst[3] = *reinterpret_cast<const __half2*>(&v.w);
    }
    __syncthreads();

    const size_t imag_base = (size_t)M_ROWS * KFREQ;
#pragma unroll
    for (int mm = 0; mm < RB; mm++) {
        const int row = m0 + mm;
        const __half* srow = sh + mm * S2_NB;
        float* ore = out + (size_t)row * KFREQ;
        float* oim = out + imag_base + (size_t)row * KFREQ;
#pragma unroll
        for (int q = 0; q < 5; q++) {
            int k = q * 256 + tid;
            if (k < KFREQ) {
                int r = k & 31, k2 = k >> 5;
                __half2 hv = *reinterpret_cast<const __half2*>(
                    srow + r * SLICE_H + 2 * k2);
                float2 f = __half22float2(hv);
                ore[k] = f.x;
                oim[k] = f.y;
            }
        }
    }
}

// ---------------------------------------------------------------------------
extern "C" void kernel_launch(void* const* d_in, const int* in_sizes, int n_in,
                              void* d_out, int out_size) {
    const float* x = (const float*)d_in[0];
    float* out = (float*)d_out;

    cudaFuncSetAttribute(stage1_kernel,
                         cudaFuncAttributeMaxDynamicSharedMemorySize, S1_SMEM);
    cudaFuncSetAttribute(stage2_kernel,
                         cudaFuncAttributeMaxDynamicSharedMemorySize, S2_SMEM);
    cudaFuncSetAttribute(reorder_kernel,
                         cudaFuncAttributeMaxDynamicSharedMemorySize, RD_SMEM);

    prep_all_kernel<<<(32 * 128 * S2_NB + 255) / 256, 256>>>();

    stage1_kernel<<<M_ROWS / 4, 256, S1_SMEM>>>(x);

    dim3 g2((M_ROWS + 127) / 128, 32);           // 79 x 32
    stage2_kernel<<<g2, 128, S2_SMEM>>>();

    reorder_kernel<<<M_ROWS / RB, 256, RD_SMEM>>>(out);
}